// round 2
// baseline (speedup 1.0000x reference)
#include <cuda_runtime.h>
#include <cstdint>

// Problem constants (fixed for this problem instance)
#define BSZ   2
#define SEQ   4096
#define EMB   1024
#define DIM   64
#define HALF  64      // window_size = 129 -> half = 64
#define NROW  (BSZ*SEQ)   // 8192

// Scratch for Q, K, V projections (allocation-free rule: __device__ globals)
__device__ float g_Q[NROW * DIM];
__device__ float g_K[NROW * DIM];
__device__ float g_V[NROW * DIM];

// ---------------------------------------------------------------------------
// Packed f32x2 helpers (Blackwell FFMA2: 2 FMA lanes per fma-pipe issue).
// Plain FFMA peaks at 64 FMA/cyc/SM (rt_SMSP=2); f32x2 doubles that.
// ---------------------------------------------------------------------------
__device__ __forceinline__ unsigned long long pack2(float x, float y) {
    unsigned long long r;
    asm("mov.b64 %0, {%1, %2};" : "=l"(r) : "f"(x), "f"(y));
    return r;
}
__device__ __forceinline__ unsigned long long ffma2(unsigned long long a,
                                                    unsigned long long b,
                                                    unsigned long long c) {
    unsigned long long d;
    asm("fma.rn.f32x2 %0, %1, %2, %3;" : "=l"(d) : "l"(a), "l"(b), "l"(c));
    return d;
}
__device__ __forceinline__ float2 unpack2(unsigned long long v) {
    float2 f;
    asm("mov.b64 {%0, %1}, %2;" : "=f"(f.x), "=f"(f.y) : "l"(v));
    return f;
}

// ---------------------------------------------------------------------------
// Kernel 1: fused QKV projection.
// C[8192 x 192] = X[8192 x 1024] @ [Wq | Wk | Wv] + bias
// Tile: BM=64 rows x 192 cols per CTA, BK=32, grid = 128 CTAs, 256 threads.
// Each thread: 4 rows x 12 cols = 48 outputs, held as 4x6 packed f32x2 accs.
// ---------------------------------------------------------------------------
__global__ __launch_bounds__(256) void qkv_kernel(
    const float* __restrict__ x,
    const float* __restrict__ Wq, const float* __restrict__ bq,
    const float* __restrict__ Wk, const float* __restrict__ bk,
    const float* __restrict__ Wv, const float* __restrict__ bv)
{
    __shared__ float Xs[32 * 64];    // [k][m]  (transposed for LDS128 on m)
    __shared__ float Ws[32 * 192];   // [k][col] cols: 0-63 Wq, 64-127 Wk, 128-191 Wv

    const int t  = threadIdx.x;
    const int m0 = blockIdx.x * 64;
    const int tx = t & 15;           // col group (12 cols each)
    const int ty = t >> 4;           // row group (4 rows each)
    const int col0 = tx * 12;
    const int r0   = ty * 4;

    unsigned long long acc[4][6];
#pragma unroll
    for (int r = 0; r < 4; r++)
#pragma unroll
        for (int c = 0; c < 6; c++) acc[r][c] = 0ull;

    for (int kt = 0; kt < EMB; kt += 32) {
        // --- load X tile (64 rows x 32 k), store transposed [k][m] ---
#pragma unroll
        for (int i = 0; i < 2; i++) {
            int idx = t + i * 256;            // 512 float4 total
            int row = idx >> 3, c4 = idx & 7;
            float4 v = *(const float4*)&x[(m0 + row) * EMB + kt + c4 * 4];
            Xs[(c4 * 4 + 0) * 64 + row] = v.x;
            Xs[(c4 * 4 + 1) * 64 + row] = v.y;
            Xs[(c4 * 4 + 2) * 64 + row] = v.z;
            Xs[(c4 * 4 + 3) * 64 + row] = v.w;
        }
        // --- load W tiles (32 k x 64 each of 3 matrices) ---
        {
#pragma unroll
            for (int i = 0; i < 2; i++) {
                int idx = t + i * 256;          // 512 float4 per matrix
                int row = idx >> 4, c4 = idx & 15;
                float4 a = *(const float4*)&Wq[(kt + row) * DIM + c4 * 4];
                float4 b = *(const float4*)&Wk[(kt + row) * DIM + c4 * 4];
                float4 c = *(const float4*)&Wv[(kt + row) * DIM + c4 * 4];
                *(float4*)&Ws[row * 192 +   0 + c4 * 4] = a;
                *(float4*)&Ws[row * 192 +  64 + c4 * 4] = b;
                *(float4*)&Ws[row * 192 + 128 + c4 * 4] = c;
            }
        }
        __syncthreads();

#pragma unroll 8
        for (int k = 0; k < 32; k++) {
            float4 A = *(const float4*)&Xs[k * 64 + r0];
            const ulonglong2* Bp = (const ulonglong2*)&Ws[k * 192 + col0];
            ulonglong2 B0 = Bp[0], B1 = Bp[1], B2 = Bp[2];
            unsigned long long bb[6] = {B0.x, B0.y, B1.x, B1.y, B2.x, B2.y};
            unsigned long long aa[4] = {pack2(A.x, A.x), pack2(A.y, A.y),
                                        pack2(A.z, A.z), pack2(A.w, A.w)};
#pragma unroll
            for (int r = 0; r < 4; r++)
#pragma unroll
                for (int c = 0; c < 6; c++)
                    acc[r][c] = ffma2(aa[r], bb[c], acc[r][c]);
        }
        __syncthreads();
    }

    // --- epilogue: bias + route to Q/K/V scratch ---
#pragma unroll
    for (int r = 0; r < 4; r++) {
        int m = m0 + r0 + r;
#pragma unroll
        for (int c = 0; c < 6; c++) {
            float2 v = unpack2(acc[r][c]);
            int g0 = col0 + 2 * c;
#pragma unroll
            for (int e = 0; e < 2; e++) {
                int   g   = g0 + e;
                float val = (e == 0) ? v.x : v.y;
                int   mat = g >> 6;
                int   d   = g & 63;
                if (mat == 0)      g_Q[m * DIM + d] = val + bq[d];
                else if (mat == 1) g_K[m * DIM + d] = val + bk[d];
                else               g_V[m * DIM + d] = val + bv[d];
            }
        }
    }
}

// ---------------------------------------------------------------------------
// Kernel 2: fused sliding-window attention.
// Per CTA: 64 queries of one batch; key range = 64 + 128 = 192 positions.
// smem: Qs[64][64] (d-major) + KV buffer (K d-major, then reused for V
// k-major) + P[64][192]. Total 112 KB -> dynamic smem.
// ---------------------------------------------------------------------------
#define SMEM_ATTN ((64*64 + 192*64 + 64*192) * 4)   // 114688 bytes

__global__ __launch_bounds__(256) void attn_kernel(float* __restrict__ out)
{
    extern __shared__ float sm[];
    float* Qs = sm;            // [64][64]  : Qs[d*64 + q]
    float* KV = sm + 4096;     // K phase: [64][192] Ks[d*192+k]; V phase: [192][64] Vs[k*64+d]
    float* Ps = KV + 12288;    // [64][192] : Ps[q*192 + k]

    const int t  = threadIdx.x;
    const int m0 = blockIdx.x * 64;          // global row (B*S flattened)
    const int b  = blockIdx.x >> 6;          // 64 tiles per batch
    const int s0 = m0 - b * SEQ;             // query start within batch

    // --- load Q tile transposed (d-major) ---
#pragma unroll
    for (int i = 0; i < 4; i++) {
        int idx = t + i * 256;               // 1024 float4 (64 rows x 16)
        int q = idx >> 4, c4 = idx & 15;
        float4 v = *(const float4*)&g_Q[(m0 + q) * DIM + c4 * 4];
        Qs[(c4 * 4 + 0) * 64 + q] = v.x;
        Qs[(c4 * 4 + 1) * 64 + q] = v.y;
        Qs[(c4 * 4 + 2) * 64 + q] = v.z;
        Qs[(c4 * 4 + 3) * 64 + q] = v.w;
    }
    // --- load K range transposed (d-major), zero-filled out of bounds ---
#pragma unroll
    for (int i = 0; i < 12; i++) {
        int idx = t + i * 256;               // 3072 float4 (192 rows x 16)
        int k = idx >> 4, c4 = idx & 15;
        int s = s0 - HALF + k;
        float4 v = make_float4(0.f, 0.f, 0.f, 0.f);
        if (s >= 0 && s < SEQ)
            v = *(const float4*)&g_K[(b * SEQ + s) * DIM + c4 * 4];
        KV[(c4 * 4 + 0) * 192 + k] = v.x;
        KV[(c4 * 4 + 1) * 192 + k] = v.y;
        KV[(c4 * 4 + 2) * 192 + k] = v.z;
        KV[(c4 * 4 + 3) * 192 + k] = v.w;
    }
    __syncthreads();

    // --- scores: S[64 x 192] = Q @ K^T, contraction over d=64 ---
    {
        const int tx = t & 15, ty = t >> 4;
        const int kc0 = tx * 12, qr0 = ty * 4;
        unsigned long long acc[4][6];
#pragma unroll
        for (int r = 0; r < 4; r++)
#pragma unroll
            for (int c = 0; c < 6; c++) acc[r][c] = 0ull;

#pragma unroll 8
        for (int d = 0; d < 64; d++) {
            float4 A = *(const float4*)&Qs[d * 64 + qr0];
            const ulonglong2* Bp = (const ulonglong2*)&KV[d * 192 + kc0];
            ulonglong2 B0 = Bp[0], B1 = Bp[1], B2 = Bp[2];
            unsigned long long bb[6] = {B0.x, B0.y, B1.x, B1.y, B2.x, B2.y};
            unsigned long long aa[4] = {pack2(A.x, A.x), pack2(A.y, A.y),
                                        pack2(A.z, A.z), pack2(A.w, A.w)};
#pragma unroll
            for (int r = 0; r < 4; r++)
#pragma unroll
                for (int c = 0; c < 6; c++)
                    acc[r][c] = ffma2(aa[r], bb[c], acc[r][c]);
        }
        // scale (1/sqrt(1024) = 1/32), mask, write to Ps
#pragma unroll
        for (int r = 0; r < 4; r++) {
            int q = qr0 + r;
#pragma unroll
            for (int c = 0; c < 6; c++) {
                float2 v = unpack2(acc[r][c]);
#pragma unroll
                for (int e = 0; e < 2; e++) {
                    int   kk  = kc0 + 2 * c + e;
                    float val = (e == 0) ? v.x : v.y;
                    int   s   = s0 - HALF + kk;
                    int   dlt = kk - q;      // key - query in window coords
                    bool valid = (dlt >= 0) && (dlt <= 2 * HALF) &&
                                 (s >= 0) && (s < SEQ);
                    Ps[q * 192 + kk] = valid ? val * 0.03125f : -3.0e38f;
                }
            }
        }
    }
    __syncthreads();   // all K reads done; KV buffer free for V

    // --- load V (natural k-major layout) into KV, overlapped with softmax ---
#pragma unroll
    for (int i = 0; i < 12; i++) {
        int idx = t + i * 256;
        int k = idx >> 4, c4 = idx & 15;
        int s = s0 - HALF + k;
        float4 v = make_float4(0.f, 0.f, 0.f, 0.f);
        if (s >= 0 && s < SEQ)
            v = *(const float4*)&g_V[(b * SEQ + s) * DIM + c4 * 4];
        *(float4*)&KV[k * 64 + c4 * 4] = v;
    }

    // --- softmax: 4 threads per row, 48 cols each ---
    {
        int row = t >> 2, seg = t & 3;
        float* rp = &Ps[row * 192 + seg * 48];
        float mx = -3.0e38f;
#pragma unroll 8
        for (int j = 0; j < 48; j++) mx = fmaxf(mx, rp[j]);
        mx = fmaxf(mx, __shfl_xor_sync(0xffffffffu, mx, 1));
        mx = fmaxf(mx, __shfl_xor_sync(0xffffffffu, mx, 2));
        float sum = 0.f;
#pragma unroll 8
        for (int j = 0; j < 48; j++) {
            float e = __expf(rp[j] - mx);
            rp[j] = e;
            sum += e;
        }
        sum += __shfl_xor_sync(0xffffffffu, sum, 1);
        sum += __shfl_xor_sync(0xffffffffu, sum, 2);
        float inv = 1.0f / sum;
#pragma unroll 8
        for (int j = 0; j < 48; j++) rp[j] *= inv;
    }
    __syncthreads();

    // --- output: O[64 x 64] = P[64 x 192] @ V[192 x 64] ---
    {
        const int dc0 = (t & 15) * 4, qr0 = (t >> 4) * 4;
        unsigned long long o[4][2];
#pragma unroll
        for (int r = 0; r < 4; r++) { o[r][0] = 0ull; o[r][1] = 0ull; }

#pragma unroll 4
        for (int k = 0; k < 192; k++) {
            ulonglong2 B = *(const ulonglong2*)&KV[k * 64 + dc0];
#pragma unroll
            for (int r = 0; r < 4; r++) {
                float p = Ps[(qr0 + r) * 192 + k];
                unsigned long long pp = pack2(p, p);
                o[r][0] = ffma2(pp, B.x, o[r][0]);
                o[r][1] = ffma2(pp, B.y, o[r][1]);
            }
        }
#pragma unroll
        for (int r = 0; r < 4; r++) {
            float2 v0 = unpack2(o[r][0]);
            float2 v1 = unpack2(o[r][1]);
            float4 res = make_float4(v0.x, v0.y, v1.x, v1.y);
            *(float4*)&out[(m0 + qr0 + r) * DIM + dc0] = res;
        }
    }
}

// ---------------------------------------------------------------------------
extern "C" void kernel_launch(void* const* d_in, const int* in_sizes, int n_in,
                              void* d_out, int out_size)
{
    const float* x  = (const float*)d_in[0];
    const float* Wq = (const float*)d_in[1];
    const float* bq = (const float*)d_in[2];
    const float* Wk = (const float*)d_in[3];
    const float* bk = (const float*)d_in[4];
    const float* Wv = (const float*)d_in[5];
    const float* bv = (const float*)d_in[6];
    // d_in[7] = window_size (129), compile-time constant here.

    cudaFuncSetAttribute(attn_kernel,
                         cudaFuncAttributeMaxDynamicSharedMemorySize, SMEM_ATTN);

    qkv_kernel<<<NROW / 64, 256>>>(x, Wq, bq, Wk, bk, Wv, bv);
    attn_kernel<<<NROW / 64, 256, SMEM_ATTN>>>((float*)d_out);
}

// round 5
// speedup vs baseline: 2.1135x; 2.1135x over previous
#include <cuda_runtime.h>
#include <cuda_bf16.h>
#include <cstdint>

// Problem constants
#define BSZ   2
#define SEQ   4096
#define EMB   1024
#define DIM   64
#define HALF  64            // window 129 -> half 64
#define NROW  (BSZ*SEQ)     // 8192

// Scratch (__device__ globals: allocation-free rule)
__device__ float g_Q[NROW * DIM];
__device__ float g_K[NROW * DIM];
__device__ float g_V[NROW * DIM];
// W transposed+split: rows n=0..191 (Q|K|V), cols k=0..1023, bf16 hi/lo
__device__ __nv_bfloat16 g_Wt_hi[192 * EMB];
__device__ __nv_bfloat16 g_Wt_lo[192 * EMB];

#define SW128(o) ((o) ^ (((o) >> 3) & 0x70))

__device__ __forceinline__ uint32_t smem_u32(const void* p) {
    uint32_t a;
    asm("{ .reg .u64 t; cvta.to.shared.u64 t, %1; cvt.u32.u64 %0, t; }"
        : "=r"(a) : "l"(p));
    return a;
}
__device__ __forceinline__ void ldsm_x4(uint32_t* r, uint32_t addr) {
    asm volatile("ldmatrix.sync.aligned.m8n8.x4.shared.b16 {%0,%1,%2,%3}, [%4];"
                 : "=r"(r[0]), "=r"(r[1]), "=r"(r[2]), "=r"(r[3]) : "r"(addr));
}
__device__ __forceinline__ void mma16816(float* d, const uint32_t* a,
                                         const uint32_t* b) {
    asm volatile(
        "mma.sync.aligned.m16n8k16.row.col.f32.bf16.bf16.f32 "
        "{%0,%1,%2,%3}, {%4,%5,%6,%7}, {%8,%9}, {%0,%1,%2,%3};"
        : "+f"(d[0]), "+f"(d[1]), "+f"(d[2]), "+f"(d[3])
        : "r"(a[0]), "r"(a[1]), "r"(a[2]), "r"(a[3]), "r"(b[0]), "r"(b[1]));
}
__device__ __forceinline__ void cp16(uint32_t dst, const void* src) {
    asm volatile("cp.async.cg.shared.global [%0], [%1], 16;"
                 :: "r"(dst), "l"(src));
}
__device__ __forceinline__ uint32_t bf2u(__nv_bfloat162 h) {
    return *reinterpret_cast<uint32_t*>(&h);
}

// ---------------------------------------------------------------------------
// Kernel 0: transpose + bf16-split W into g_Wt_hi/lo.  Wt[n][k] = W[k][n].
// ---------------------------------------------------------------------------
__global__ __launch_bounds__(256) void wprep_kernel(
    const float* __restrict__ Wq, const float* __restrict__ Wk,
    const float* __restrict__ Wv)
{
    __shared__ float S[64 * 65];
    const int bx  = blockIdx.x;
    const int mat = bx >> 4;
    const int kt  = (bx & 15) * 64;
    const float* Wm = (mat == 0) ? Wq : (mat == 1 ? Wk : Wv);
    const int tid = threadIdx.x;

#pragma unroll
    for (int i = 0; i < 4; i++) {
        int idx = tid + i * 256;               // 1024 float4
        int kk = idx >> 4, c4 = idx & 15;
        float4 v = *(const float4*)&Wm[(kt + kk) * DIM + c4 * 4];
        S[kk * 65 + c4 * 4 + 0] = v.x;
        S[kk * 65 + c4 * 4 + 1] = v.y;
        S[kk * 65 + c4 * 4 + 2] = v.z;
        S[kk * 65 + c4 * 4 + 3] = v.w;
    }
    __syncthreads();
#pragma unroll
    for (int i = 0; i < 16; i++) {
        int idx = tid + i * 256;               // 4096 elems
        int n = idx >> 6, kk = idx & 63;
        float v = S[kk * 65 + n];
        __nv_bfloat16 h = __float2bfloat16(v);
        __nv_bfloat16 l = __float2bfloat16(v - __bfloat162float(h));
        g_Wt_hi[(mat * 64 + n) * EMB + kt + kk] = h;
        g_Wt_lo[(mat * 64 + n) * EMB + kt + kk] = l;
    }
}

// ---------------------------------------------------------------------------
// Kernel 1: QKV projection via mma.sync bf16 (split-bf16, 3 terms).
// C[8192 x 192] = X @ [Wq|Wk|Wv] + bias.  BM=64, BN=192, KT=64, 8 warps.
// Warp tile 32x48: 2 m-frags x 6 n-frags. Double-buffered smem.
// ---------------------------------------------------------------------------
#define KT    64
#define AH_O  0
#define AL_O  8192
#define BH_O  16384
#define BL_O  40960
#define BUFSZ 65536
#define QKV_SMEM (2*BUFSZ)    // 131072

__global__ __launch_bounds__(256) void qkv_kernel(
    const float* __restrict__ x,
    const float* __restrict__ bq, const float* __restrict__ bk,
    const float* __restrict__ bv)
{
    extern __shared__ char sm[];
    const uint32_t sb = smem_u32(sm);
    const int tid  = threadIdx.x;
    const int m0   = blockIdx.x * 64;
    const int w    = tid >> 5, lane = tid & 31;
    const int mrow = (w & 1) * 32;
    const int ncol = (w >> 1) * 48;

    // per-lane ldmatrix row/half decomposition
    const int rA = lane & 15, hA = lane >> 4;                 // A x4
    const int rB = (lane & 7) + ((lane >> 4) << 3);           // B x4
    const int hB = (lane >> 3) & 1;

    float acc[2][6][4];
#pragma unroll
    for (int i = 0; i < 2; i++)
#pragma unroll
        for (int j = 0; j < 6; j++)
#pragma unroll
            for (int q = 0; q < 4; q++) acc[i][j][q] = 0.f;

    float4 xr[4];

    // ---- helpers (macros over locals) ----
#define LOAD_X(T)                                                          \
    {   int k0 = (T) * KT;                                                 \
        _Pragma("unroll")                                                  \
        for (int i = 0; i < 4; i++) {                                      \
            int idx = tid + i * 256;                                       \
            int row = idx >> 4, c4 = idx & 15;                             \
            xr[i] = *(const float4*)&x[(size_t)(m0 + row) * EMB + k0 + c4 * 4]; \
        } }

#define ISSUE_W(T, BO)                                                     \
    {   int k0 = (T) * KT;                                                 \
        _Pragma("unroll")                                                  \
        for (int i = 0; i < 6; i++) {                                      \
            int idx = tid + i * 256;                                       \
            int n = idx >> 3, c = idx & 7;                                 \
            uint32_t doff = SW128((uint32_t)(n * 128 + c * 16));           \
            cp16(sb + (BO) + BH_O + doff, &g_Wt_hi[n * EMB + k0 + c * 8]); \
            cp16(sb + (BO) + BL_O + doff, &g_Wt_lo[n * EMB + k0 + c * 8]); \
        }                                                                  \
        asm volatile("cp.async.commit_group;" ::: "memory"); }

#define STORE_X(BO)                                                        \
    {   _Pragma("unroll")                                                  \
        for (int i = 0; i < 4; i++) {                                      \
            int idx = tid + i * 256;                                       \
            int row = idx >> 4, c4 = idx & 15;                             \
            float4 v = xr[i];                                              \
            __nv_bfloat162 h01 = __floats2bfloat162_rn(v.x, v.y);          \
            __nv_bfloat162 h23 = __floats2bfloat162_rn(v.z, v.w);          \
            float2 f01 = __bfloat1622float2(h01);                          \
            float2 f23 = __bfloat1622float2(h23);                          \
            __nv_bfloat162 l01 = __floats2bfloat162_rn(v.x - f01.x, v.y - f01.y); \
            __nv_bfloat162 l23 = __floats2bfloat162_rn(v.z - f23.x, v.w - f23.y); \
            uint32_t off = SW128((uint32_t)(row * 128 + c4 * 8));          \
            *(uint2*)(sm + (BO) + AH_O + off) = make_uint2(bf2u(h01), bf2u(h23)); \
            *(uint2*)(sm + (BO) + AL_O + off) = make_uint2(bf2u(l01), bf2u(l23)); \
        } }

#define COMPUTE(BO)                                                        \
    {   _Pragma("unroll")                                                  \
        for (int s = 0; s < 4; s++) {                                      \
            uint32_t Ahf[2][4], Alf[2][4];                                 \
            _Pragma("unroll")                                              \
            for (int mi = 0; mi < 2; mi++) {                               \
                uint32_t ao = SW128((uint32_t)((mrow + mi * 16 + rA) * 128 \
                                               + s * 32 + hA * 16));       \
                ldsm_x4(Ahf[mi], sb + (BO) + AH_O + ao);                   \
                ldsm_x4(Alf[mi], sb + (BO) + AL_O + ao);                   \
            }                                                              \
            uint32_t Bhf[3][4], Blf[3][4];                                 \
            _Pragma("unroll")                                              \
            for (int p = 0; p < 3; p++) {                                  \
                uint32_t bo = SW128((uint32_t)((ncol + p * 16 + rB) * 128  \
                                               + s * 32 + hB * 16));       \
                ldsm_x4(Bhf[p], sb + (BO) + BH_O + bo);                    \
                ldsm_x4(Blf[p], sb + (BO) + BL_O + bo);                    \
            }                                                              \
            _Pragma("unroll")                                              \
            for (int mi = 0; mi < 2; mi++)                                 \
            _Pragma("unroll")                                              \
            for (int p = 0; p < 3; p++) {                                  \
                mma16816(acc[mi][2 * p + 0], Ahf[mi], &Bhf[p][0]);         \
                mma16816(acc[mi][2 * p + 1], Ahf[mi], &Bhf[p][2]);         \
                mma16816(acc[mi][2 * p + 0], Ahf[mi], &Blf[p][0]);         \
                mma16816(acc[mi][2 * p + 1], Ahf[mi], &Blf[p][2]);         \
                mma16816(acc[mi][2 * p + 0], Alf[mi], &Bhf[p][0]);         \
                mma16816(acc[mi][2 * p + 1], Alf[mi], &Bhf[p][2]);         \
            }                                                              \
        } }

    // ---- prologue: tile 0 ----
    LOAD_X(0);
    ISSUE_W(0, 0);
    asm volatile("cp.async.wait_group 0;" ::: "memory");
    STORE_X(0);
    __syncthreads();

    // ---- main loop, double-buffered ----
    for (int t = 0; t < EMB / KT; t++) {
        uint32_t cur = (uint32_t)(t & 1) * BUFSZ;
        uint32_t nxt = (uint32_t)((t + 1) & 1) * BUFSZ;
        if (t < EMB / KT - 1) {
            LOAD_X(t + 1);
            ISSUE_W(t + 1, nxt);
        }
        COMPUTE(cur);
        if (t < EMB / KT - 1) {
            asm volatile("cp.async.wait_group 0;" ::: "memory");
            STORE_X(nxt);
        }
        __syncthreads();
    }

    // ---- epilogue: bias + store to g_Q/g_K/g_V ----
    {
        const int mr  = lane >> 2;
        const int nc2 = (lane & 3) * 2;
#pragma unroll
        for (int mi = 0; mi < 2; mi++) {
            int m = m0 + mrow + mi * 16 + mr;
#pragma unroll
            for (int ni = 0; ni < 6; ni++) {
                int n0  = ncol + ni * 8 + nc2;
                int mat = n0 >> 6, d0 = n0 & 63;
                const float* bias = (mat == 0) ? bq : (mat == 1 ? bk : bv);
                float*       dst  = (mat == 0) ? g_Q : (mat == 1 ? g_K : g_V);
                float b0 = bias[d0], b1 = bias[d0 + 1];
                float2 v0 = make_float2(acc[mi][ni][0] + b0, acc[mi][ni][1] + b1);
                float2 v1 = make_float2(acc[mi][ni][2] + b0, acc[mi][ni][3] + b1);
                *(float2*)&dst[(size_t)m * DIM + d0]       = v0;
                *(float2*)&dst[(size_t)(m + 8) * DIM + d0] = v1;
            }
        }
    }
}

// ---------------------------------------------------------------------------
// Packed f32x2 helpers (attention kernel)
// ---------------------------------------------------------------------------
__device__ __forceinline__ unsigned long long pack2(float x, float y) {
    unsigned long long r;
    asm("mov.b64 %0, {%1, %2};" : "=l"(r) : "f"(x), "f"(y));
    return r;
}
__device__ __forceinline__ unsigned long long ffma2(unsigned long long a,
                                                    unsigned long long b,
                                                    unsigned long long c) {
    unsigned long long d;
    asm("fma.rn.f32x2 %0, %1, %2, %3;" : "=l"(d) : "l"(a), "l"(b), "l"(c));
    return d;
}
__device__ __forceinline__ float2 unpack2(unsigned long long v) {
    float2 f;
    asm("mov.b64 {%0, %1}, %2;" : "=f"(f.x), "=f"(f.y) : "l"(v));
    return f;
}

// ---------------------------------------------------------------------------
// Kernel 2: fused sliding-window attention (R2 passing version, unchanged)
// ---------------------------------------------------------------------------
#define SMEM_ATTN ((64*64 + 192*64 + 64*192) * 4)   // 114688 bytes

__global__ __launch_bounds__(256) void attn_kernel(float* __restrict__ out)
{
    extern __shared__ float smf[];
    float* Qs = smf;           // [64][64]  d-major
    float* KV = smf + 4096;    // K: [64][192] d-major; then V: [192][64]
    float* Ps = KV + 12288;    // [64][192]

    const int t  = threadIdx.x;
    const int m0 = blockIdx.x * 64;
    const int b  = blockIdx.x >> 6;
    const int s0 = m0 - b * SEQ;

#pragma unroll
    for (int i = 0; i < 4; i++) {
        int idx = t + i * 256;
        int q = idx >> 4, c4 = idx & 15;
        float4 v = *(const float4*)&g_Q[(m0 + q) * DIM + c4 * 4];
        Qs[(c4 * 4 + 0) * 64 + q] = v.x;
        Qs[(c4 * 4 + 1) * 64 + q] = v.y;
        Qs[(c4 * 4 + 2) * 64 + q] = v.z;
        Qs[(c4 * 4 + 3) * 64 + q] = v.w;
    }
#pragma unroll
    for (int i = 0; i < 12; i++) {
        int idx = t + i * 256;
        int k = idx >> 4, c4 = idx & 15;
        int s = s0 - HALF + k;
        float4 v = make_float4(0.f, 0.f, 0.f, 0.f);
        if (s >= 0 && s < SEQ)
            v = *(const float4*)&g_K[(b * SEQ + s) * DIM + c4 * 4];
        KV[(c4 * 4 + 0) * 192 + k] = v.x;
        KV[(c4 * 4 + 1) * 192 + k] = v.y;
        KV[(c4 * 4 + 2) * 192 + k] = v.z;
        KV[(c4 * 4 + 3) * 192 + k] = v.w;
    }
    __syncthreads();

    {
        const int tx = t & 15, ty = t >> 4;
        const int kc0 = tx * 12, qr0 = ty * 4;
        unsigned long long acc[4][6];
#pragma unroll
        for (int r = 0; r < 4; r++)
#pragma unroll
            for (int c = 0; c < 6; c++) acc[r][c] = 0ull;

#pragma unroll 8
        for (int d = 0; d < 64; d++) {
            float4 A = *(const float4*)&Qs[d * 64 + qr0];
            const ulonglong2* Bp = (const ulonglong2*)&KV[d * 192 + kc0];
            ulonglong2 B0 = Bp[0], B1 = Bp[1], B2 = Bp[2];
            unsigned long long bb[6] = {B0.x, B0.y, B1.x, B1.y, B2.x, B2.y};
            unsigned long long aa[4] = {pack2(A.x, A.x), pack2(A.y, A.y),
                                        pack2(A.z, A.z), pack2(A.w, A.w)};
#pragma unroll
            for (int r = 0; r < 4; r++)
#pragma unroll
                for (int c = 0; c < 6; c++)
                    acc[r][c] = ffma2(aa[r], bb[c], acc[r][c]);
        }
#pragma unroll
        for (int r = 0; r < 4; r++) {
            int q = qr0 + r;
#pragma unroll
            for (int c = 0; c < 6; c++) {
                float2 v = unpack2(acc[r][c]);
#pragma unroll
                for (int e = 0; e < 2; e++) {
                    int   kk  = kc0 + 2 * c + e;
                    float val = (e == 0) ? v.x : v.y;
                    int   s   = s0 - HALF + kk;
                    int   dlt = kk - q;
                    bool valid = (dlt >= 0) && (dlt <= 2 * HALF) &&
                                 (s >= 0) && (s < SEQ);
                    Ps[q * 192 + kk] = valid ? val * 0.03125f : -3.0e38f;
                }
            }
        }
    }
    __syncthreads();

#pragma unroll
    for (int i = 0; i < 12; i++) {
        int idx = t + i * 256;
        int k = idx >> 4, c4 = idx & 15;
        int s = s0 - HALF + k;
        float4 v = make_float4(0.f, 0.f, 0.f, 0.f);
        if (s >= 0 && s < SEQ)
            v = *(const float4*)&g_V[(b * SEQ + s) * DIM + c4 * 4];
        *(float4*)&KV[k * 64 + c4 * 4] = v;
    }

    {
        int row = t >> 2, seg = t & 3;
        float* rp = &Ps[row * 192 + seg * 48];
        float mx = -3.0e38f;
#pragma unroll 8
        for (int j = 0; j < 48; j++) mx = fmaxf(mx, rp[j]);
        mx = fmaxf(mx, __shfl_xor_sync(0xffffffffu, mx, 1));
        mx = fmaxf(mx, __shfl_xor_sync(0xffffffffu, mx, 2));
        float sum = 0.f;
#pragma unroll 8
        for (int j = 0; j < 48; j++) {
            float e = __expf(rp[j] - mx);
            rp[j] = e;
            sum += e;
        }
        sum += __shfl_xor_sync(0xffffffffu, sum, 1);
        sum += __shfl_xor_sync(0xffffffffu, sum, 2);
        float inv = 1.0f / sum;
#pragma unroll 8
        for (int j = 0; j < 48; j++) rp[j] *= inv;
    }
    __syncthreads();

    {
        const int dc0 = (t & 15) * 4, qr0 = (t >> 4) * 4;
        unsigned long long o[4][2];
#pragma unroll
        for (int r = 0; r < 4; r++) { o[r][0] = 0ull; o[r][1] = 0ull; }

#pragma unroll 4
        for (int k = 0; k < 192; k++) {
            ulonglong2 B = *(const ulonglong2*)&KV[k * 64 + dc0];
#pragma unroll
            for (int r = 0; r < 4; r++) {
                float p = Ps[(qr0 + r) * 192 + k];
                unsigned long long pp = pack2(p, p);
                o[r][0] = ffma2(pp, B.x, o[r][0]);
                o[r][1] = ffma2(pp, B.y, o[r][1]);
            }
        }
#pragma unroll
        for (int r = 0; r < 4; r++) {
            float2 v0 = unpack2(o[r][0]);
            float2 v1 = unpack2(o[r][1]);
            float4 res = make_float4(v0.x, v0.y, v1.x, v1.y);
            *(float4*)&out[(m0 + qr0 + r) * DIM + dc0] = res;
        }
    }
}

// ---------------------------------------------------------------------------
extern "C" void kernel_launch(void* const* d_in, const int* in_sizes, int n_in,
                              void* d_out, int out_size)
{
    const float* x  = (const float*)d_in[0];
    const float* Wq = (const float*)d_in[1];
    const float* bq = (const float*)d_in[2];
    const float* Wk = (const float*)d_in[3];
    const float* bk = (const float*)d_in[4];
    const float* Wv = (const float*)d_in[5];
    const float* bv = (const float*)d_in[6];

    cudaFuncSetAttribute(qkv_kernel,
                         cudaFuncAttributeMaxDynamicSharedMemorySize, QKV_SMEM);
    cudaFuncSetAttribute(attn_kernel,
                         cudaFuncAttributeMaxDynamicSharedMemorySize, SMEM_ATTN);

    wprep_kernel<<<48, 256>>>(Wq, Wk, Wv);
    qkv_kernel<<<NROW / 64, 256, QKV_SMEM>>>(x, bq, bk, bv);
    attn_kernel<<<NROW / 64, 256, SMEM_ATTN>>>((float*)d_out);
}